// round 7
// baseline (speedup 1.0000x reference)
#include <cuda_runtime.h>
#include <cstddef>
#include <cstdint>

#define B_ 512
#define T_ 1024
#define U_ 128
#define RSTR 144   // padded h row stride in floats (128 + 4 pad per 32-block)

typedef unsigned long long ull;
typedef unsigned int uint;

// Allocation-free scratch: two 256MB staging buffers as device globals (.bss).
__device__ float g_pbuf[(size_t)T_ * B_ * U_];  // px1, later reused for p2
__device__ float g_h1[(size_t)T_ * B_ * U_];    // full h1 sequence

// ---------- packed f32x2 helpers (Blackwell, PTX-only) ----------
__device__ __forceinline__ ull bc2(float v) {
    ull r; asm("mov.b64 %0, {%1,%1};" : "=l"(r) : "f"(v)); return r;
}
__device__ __forceinline__ ull pack2(float a, float b) {
    ull r; asm("mov.b64 %0, {%1,%2};" : "=l"(r) : "f"(a), "f"(b)); return r;
}
__device__ __forceinline__ void fma2(ull& d, ull a, ull b) {
    asm("fma.rn.f32x2 %0, %1, %2, %0;" : "+l"(d) : "l"(a), "l"(b));
}
__device__ __forceinline__ ull add2(ull a, ull b) {
    ull r; asm("add.rn.f32x2 %0, %1, %2;" : "=l"(r) : "l"(a), "l"(b)); return r;
}
__device__ __forceinline__ void unpk(ull v, float& lo, float& hi) {
    asm("mov.b64 {%0,%1}, %2;" : "=f"(lo), "=f"(hi) : "l"(v));
}

// ============================================================================
// Parallel GEMM + bias (unchanged — known-good from R4/R6 passing runs)
// ============================================================================
template <int KD, bool XLAY>
__global__ __launch_bounds__(256, 2)
void gemm_bias(const float* __restrict__ A, const float* __restrict__ W,
               const float* __restrict__ bias, float* __restrict__ out)
{
    extern __shared__ float sm[];
    float* Ws = sm;               // [KD][128]
    float* As = sm + KD * U_;     // [KD][68]
    const int tid  = threadIdx.x;
    const int row0 = blockIdx.x * 64;

    for (int i = tid; i < KD * U_; i += 256) Ws[i] = W[i];

    for (int i = tid; i < 64 * KD; i += 256) {
        int r = i / KD, k = i - r * KD;
        size_t off;
        if (XLAY) {
            int t = row0 >> 9;
            int b = (row0 & (B_ - 1)) + r;
            off = ((size_t)b * T_ + t) * KD + k;
        } else {
            off = (size_t)(row0 + r) * KD + k;
        }
        As[k * 68 + r] = A[off];
    }
    __syncthreads();

    const int u0 = (tid & 31) * 4;
    const int rb = (tid >> 5) * 8;

    ull acc[4][4];
#pragma unroll
    for (int a = 0; a < 4; a++)
#pragma unroll
        for (int b = 0; b < 4; b++) acc[a][b] = 0ULL;

#pragma unroll 4
    for (int k = 0; k < KD; k++) {
        ulonglong2 a01 = *(const ulonglong2*)(As + k * 68 + rb);
        ulonglong2 a23 = *(const ulonglong2*)(As + k * 68 + rb + 4);
        float4 w4 = *(const float4*)(Ws + k * U_ + u0);
        ull w;
        w = bc2(w4.x);
        fma2(acc[0][0], a01.x, w); fma2(acc[0][1], a01.y, w);
        fma2(acc[0][2], a23.x, w); fma2(acc[0][3], a23.y, w);
        w = bc2(w4.y);
        fma2(acc[1][0], a01.x, w); fma2(acc[1][1], a01.y, w);
        fma2(acc[1][2], a23.x, w); fma2(acc[1][3], a23.y, w);
        w = bc2(w4.z);
        fma2(acc[2][0], a01.x, w); fma2(acc[2][1], a01.y, w);
        fma2(acc[2][2], a23.x, w); fma2(acc[2][3], a23.y, w);
        w = bc2(w4.w);
        fma2(acc[3][0], a01.x, w); fma2(acc[3][1], a01.y, w);
        fma2(acc[3][2], a23.x, w); fma2(acc[3][3], a23.y, w);
    }

    float f[4][8];
#pragma unroll
    for (int uu = 0; uu < 4; uu++)
#pragma unroll
        for (int rp = 0; rp < 4; rp++) unpk(acc[uu][rp], f[uu][2 * rp], f[uu][2 * rp + 1]);

    float4 bv = *(const float4*)(bias + u0);
#pragma unroll
    for (int rr = 0; rr < 8; rr++) {
        float4 o = make_float4(f[0][rr] + bv.x, f[1][rr] + bv.y,
                               f[2][rr] + bv.z, f[3][rr] + bv.w);
        *(float4*)(out + (size_t)(row0 + rb + rr) * U_ + u0) = o;
    }
}

// ============================================================================
// Recurrence v3: h_t = relu(p_t + h_{t-1} @ Wr), p layout [t][b][u].
// 128 CTAs x 4 independent batch rows. 512 threads = 64 u-pairs x 8 k-slices.
// Each thread: 2 units x 16 k's x 4 rows -> 4 FFMA2 per LDS.128 (ratio 4:1).
// 8-lane select-fold butterfly leaves each lane owning ONE (row, unit):
//   row = ((ks>>2)&1)*2 + ((ks>>1)&1),  unit = 2*up + (ks&1).
// Ping-pong h buffers -> one barrier per step.
// ============================================================================
template <bool STOREH, bool FINAL>
__global__ __launch_bounds__(512, 1)
void recur3(const float* __restrict__ p, const float* __restrict__ Wr,
            float* __restrict__ hall, const float* __restrict__ Wd,
            const float* __restrict__ bd, float* __restrict__ dout)
{
    __shared__ __align__(16) float hs[2][4 * RSTR];
    __shared__ float part_s[4 * U_];

    const int tid = threadIdx.x;
    const int up  = tid >> 3;          // u-pair 0..63
    const int ks  = tid & 7;           // k-slice 0..7 (adjacent lanes)
    const int r0  = blockIdx.x * 4;

    const int u0 = 2 * up;             // this thread's two unit columns
    const int u1 = 2 * up + 1;

    // ownership after reduction
    const int ownR = ((ks >> 2) & 1) * 2 + ((ks >> 1) & 1);
    const int ownU = 2 * up + (ks & 1);
    const int ownUph = ownU + 4 * (ownU >> 5);

    // 8 packed k-pair weights per unit column, k = ks*16 .. ks*16+15 (loaded once)
    ull wp0[8], wp1[8];
#pragma unroll
    for (int i = 0; i < 8; i++) {
        int k = ks * 16 + 2 * i;
        wp0[i] = pack2(Wr[(size_t)k * U_ + u0], Wr[(size_t)(k + 1) * U_ + u0]);
        wp1[i] = pack2(Wr[(size_t)k * U_ + u1], Wr[(size_t)(k + 1) * U_ + u1]);
    }

    // zero initial read buffer
    for (int i = tid; i < 4 * RSTR; i += 512) hs[0][i] = 0.f;

    // per-thread p stream for the owned (row, unit)
    const float* pown = p + ((size_t)(r0 + ownR)) * U_ + ownU;
    float pv = pown[0];
    __syncthreads();

    const int ksphys = ks * 16 + 4 * (ks >> 1);   // padded slice base

    float s = 0.f;                                 // owned h value (live at loop end)

    for (int t = 0; t < T_; t++) {
        // prefetch next step's p one full step ahead
        int tn = (t < T_ - 1) ? t + 1 : t;
        float pnext = pown[(size_t)tn * B_ * U_];

        const float* hb = hs[t & 1];
        float*       hn = hs[(t + 1) & 1];

        ull a[4][2];
#pragma unroll
        for (int r = 0; r < 4; r++) { a[r][0] = 0ULL; a[r][1] = 0ULL; }

#pragma unroll
        for (int r = 0; r < 4; r++) {
            const ulonglong2* base = (const ulonglong2*)(hb + r * RSTR + ksphys);
#pragma unroll
            for (int i = 0; i < 4; i++) {
                ulonglong2 hv = base[i];
                fma2(a[r][0], hv.x, wp0[2 * i]);
                fma2(a[r][0], hv.y, wp0[2 * i + 1]);
                fma2(a[r][1], hv.x, wp1[2 * i]);
                fma2(a[r][1], hv.y, wp1[2 * i + 1]);
            }
        }

        // ---- select-fold butterfly over the 8 ks lanes (packed f32x2 domain) ----
        // round 1 (xor 4): fold row-halves {0,1} vs {2,3}
        const bool h4 = (ks & 4) != 0;
        ull s0 = h4 ? a[0][0] : a[2][0];   // rows the partner keeps
        ull s1 = h4 ? a[0][1] : a[2][1];
        ull s2 = h4 ? a[1][0] : a[3][0];
        ull s3 = h4 ? a[1][1] : a[3][1];
        s0 = __shfl_xor_sync(0xffffffffu, s0, 4);
        s1 = __shfl_xor_sync(0xffffffffu, s1, 4);
        s2 = __shfl_xor_sync(0xffffffffu, s2, 4);
        s3 = __shfl_xor_sync(0xffffffffu, s3, 4);
        ull w0 = add2(h4 ? a[2][0] : a[0][0], s0);  // (rowA, u0)
        ull w1 = add2(h4 ? a[2][1] : a[0][1], s1);  // (rowA, u1)
        ull w2 = add2(h4 ? a[3][0] : a[1][0], s2);  // (rowB, u0)
        ull w3 = add2(h4 ? a[3][1] : a[1][1], s3);  // (rowB, u1)

        // round 2 (xor 2): fold rowA vs rowB
        const bool h2 = (ks & 2) != 0;
        ull t0 = h2 ? w0 : w2;
        ull t1 = h2 ? w1 : w3;
        t0 = __shfl_xor_sync(0xffffffffu, t0, 2);
        t1 = __shfl_xor_sync(0xffffffffu, t1, 2);
        ull x0 = add2(h2 ? w2 : w0, t0);   // (ownR, u0)
        ull x1 = add2(h2 ? w3 : w1, t1);   // (ownR, u1)

        // round 3 (xor 1): fold u0 vs u1
        const bool h1 = (ks & 1) != 0;
        ull y = h1 ? x0 : x1;
        y = __shfl_xor_sync(0xffffffffu, y, 1);
        ull f = add2(h1 ? x1 : x0, y);     // final packed k-parity sum for (ownR, ownU)

        float lo, hi;
        unpk(f, lo, hi);
        s = fmaxf(lo + hi + pv, 0.f);

        hn[ownR * RSTR + ownUph] = s;
        if (STOREH)
            hall[((size_t)t * B_ + r0 + ownR) * U_ + ownU] = s;
        pv = pnext;
        __syncthreads();   // next step reads hn
    }

    if (FINAL) {
        // each thread holds its final h(ownR, ownU) in s
        part_s[ownR * U_ + ownU] = s * Wd[ownU];
        __syncthreads();
        // warp w (w<4) reduces row w
        const int wid = tid >> 5, lid = tid & 31;
        if (wid < 4) {
            const float* pr = part_s + wid * U_;
            float acc = pr[lid] + pr[lid + 32] + pr[lid + 64] + pr[lid + 96];
#pragma unroll
            for (int m = 16; m > 0; m >>= 1)
                acc += __shfl_xor_sync(0xffffffffu, acc, m);
            if (lid == 0) dout[r0 + wid] = acc + bd[0];
        }
    }
}

// ============================================================================
extern "C" void kernel_launch(void* const* d_in, const int* in_sizes, int n_in,
                              void* d_out, int out_size)
{
    (void)in_sizes; (void)n_in; (void)out_size;
    const float* x   = (const float*)d_in[0];
    const float* Wx1 = (const float*)d_in[1];
    const float* Wh1 = (const float*)d_in[2];
    const float* b1  = (const float*)d_in[3];
    const float* Wx2 = (const float*)d_in[4];
    const float* Wh2 = (const float*)d_in[5];
    const float* b2  = (const float*)d_in[6];
    const float* Wd  = (const float*)d_in[7];
    const float* bd  = (const float*)d_in[8];
    float* out = (float*)d_out;

    float *pbuf, *h1buf;
    cudaGetSymbolAddress((void**)&pbuf, g_pbuf);
    cudaGetSymbolAddress((void**)&h1buf, g_h1);

    const int ngrid = (T_ * B_) / 64;                        // 8192 tiles
    const int smemA = (64 * U_ + 64 * 68) * sizeof(float);   // 50176 B
    const int smemC = (128 * U_ + 128 * 68) * sizeof(float); // 100352 B
    cudaFuncSetAttribute(gemm_bias<64, true>,
                         cudaFuncAttributeMaxDynamicSharedMemorySize, smemA);
    cudaFuncSetAttribute(gemm_bias<128, false>,
                         cudaFuncAttributeMaxDynamicSharedMemorySize, smemC);

    // Phase A: px1 = x @ Wx1 + b1           (layout [t][b][u])
    gemm_bias<64, true><<<ngrid, 256, smemA>>>(x, Wx1, b1, pbuf);
    // Phase B: h1 recurrence, store full sequence
    recur3<true, false><<<B_ / 4, 512>>>(pbuf, Wh1, h1buf, nullptr, nullptr, nullptr);
    // Phase C: p2 = H1 @ Wx2 + b2           (overwrites pbuf)
    gemm_bias<128, false><<<ngrid, 256, smemC>>>(h1buf, Wx2, b2, pbuf);
    // Phase D: h2 recurrence + final projection
    recur3<false, true><<<B_ / 4, 512>>>(pbuf, Wh2, nullptr, Wd, bd, out);
}

// round 8
// speedup vs baseline: 1.4143x; 1.4143x over previous
#include <cuda_runtime.h>
#include <cstddef>
#include <cstdint>

#define B_ 512
#define T_ 1024
#define U_ 128
#define RSTR 144   // padded h row stride in floats (128 + 4 pad per 32-block)

typedef unsigned long long ull;
typedef unsigned int uint;

// Allocation-free scratch: two 256MB staging buffers as device globals (.bss).
__device__ float g_pbuf[(size_t)T_ * B_ * U_];  // px1
__device__ float g_p2[(size_t)T_ * B_ * U_];    // p2 (written by fused recurBC)

// ---------- packed f32x2 helpers (Blackwell, PTX-only) ----------
__device__ __forceinline__ ull bc2(float v) {
    ull r; asm("mov.b64 %0, {%1,%1};" : "=l"(r) : "f"(v)); return r;
}
__device__ __forceinline__ ull pack2(float a, float b) {
    ull r; asm("mov.b64 %0, {%1,%2};" : "=l"(r) : "f"(a), "f"(b)); return r;
}
__device__ __forceinline__ void fma2(ull& d, ull a, ull b) {
    asm("fma.rn.f32x2 %0, %1, %2, %0;" : "+l"(d) : "l"(a), "l"(b));
}
__device__ __forceinline__ void unpk(ull v, float& lo, float& hi) {
    asm("mov.b64 {%0,%1}, %2;" : "=f"(lo), "=f"(hi) : "l"(v));
}

// ============================================================================
// Parallel GEMM + bias (unchanged — known-good from R4/R6 passing runs)
// ============================================================================
template <int KD, bool XLAY>
__global__ __launch_bounds__(256, 2)
void gemm_bias(const float* __restrict__ A, const float* __restrict__ W,
               const float* __restrict__ bias, float* __restrict__ out)
{
    extern __shared__ float sm[];
    float* Ws = sm;               // [KD][128]
    float* As = sm + KD * U_;     // [KD][68]
    const int tid  = threadIdx.x;
    const int row0 = blockIdx.x * 64;

    for (int i = tid; i < KD * U_; i += 256) Ws[i] = W[i];

    for (int i = tid; i < 64 * KD; i += 256) {
        int r = i / KD, k = i - r * KD;
        size_t off;
        if (XLAY) {
            int t = row0 >> 9;
            int b = (row0 & (B_ - 1)) + r;
            off = ((size_t)b * T_ + t) * KD + k;
        } else {
            off = (size_t)(row0 + r) * KD + k;
        }
        As[k * 68 + r] = A[off];
    }
    __syncthreads();

    const int u0 = (tid & 31) * 4;
    const int rb = (tid >> 5) * 8;

    ull acc[4][4];
#pragma unroll
    for (int a = 0; a < 4; a++)
#pragma unroll
        for (int b = 0; b < 4; b++) acc[a][b] = 0ULL;

#pragma unroll 4
    for (int k = 0; k < KD; k++) {
        ulonglong2 a01 = *(const ulonglong2*)(As + k * 68 + rb);
        ulonglong2 a23 = *(const ulonglong2*)(As + k * 68 + rb + 4);
        float4 w4 = *(const float4*)(Ws + k * U_ + u0);
        ull w;
        w = bc2(w4.x);
        fma2(acc[0][0], a01.x, w); fma2(acc[0][1], a01.y, w);
        fma2(acc[0][2], a23.x, w); fma2(acc[0][3], a23.y, w);
        w = bc2(w4.y);
        fma2(acc[1][0], a01.x, w); fma2(acc[1][1], a01.y, w);
        fma2(acc[1][2], a23.x, w); fma2(acc[1][3], a23.y, w);
        w = bc2(w4.z);
        fma2(acc[2][0], a01.x, w); fma2(acc[2][1], a01.y, w);
        fma2(acc[2][2], a23.x, w); fma2(acc[2][3], a23.y, w);
        w = bc2(w4.w);
        fma2(acc[3][0], a01.x, w); fma2(acc[3][1], a01.y, w);
        fma2(acc[3][2], a23.x, w); fma2(acc[3][3], a23.y, w);
    }

    float f[4][8];
#pragma unroll
    for (int uu = 0; uu < 4; uu++)
#pragma unroll
        for (int rp = 0; rp < 4; rp++) unpk(acc[uu][rp], f[uu][2 * rp], f[uu][2 * rp + 1]);

    float4 bv = *(const float4*)(bias + u0);
#pragma unroll
    for (int rr = 0; rr < 8; rr++) {
        float4 o = make_float4(f[0][rr] + bv.x, f[1][rr] + bv.y,
                               f[2][rr] + bv.z, f[3][rr] + bv.w);
        *(float4*)(out + (size_t)(row0 + rb + rr) * U_ + u0) = o;
    }
}

// ============================================================================
// Recurrence v2 (unchanged — known-good 764us from R6). Used for phase D.
// ============================================================================
template <bool STOREH, bool FINAL>
__global__ __launch_bounds__(256, 1)
void recur2(const float* __restrict__ p, const float* __restrict__ Wr,
            float* __restrict__ hall, const float* __restrict__ Wd,
            const float* __restrict__ bd, float* __restrict__ dout)
{
    __shared__ __align__(16) float hs[2][4 * RSTR];
    __shared__ float4 part_s[U_];

    const int tid = threadIdx.x;
    const int u   = tid >> 1;
    const int ks  = tid & 1;
    const int r0  = blockIdx.x * 4;
    const bool wr = (ks == 0);

    ull wp[32];
#pragma unroll
    for (int i = 0; i < 32; i++) {
        float a = Wr[(size_t)(ks * 64 + 2 * i) * U_ + u];
        float b = Wr[(size_t)(ks * 64 + 2 * i + 1) * U_ + u];
        wp[i] = pack2(a, b);
    }

    for (int i = tid; i < 4 * RSTR; i += 256) hs[0][i] = 0.f;

    const int uph = u + 4 * (u >> 5);

    const float* prow = p + (size_t)r0 * U_ + u;
    float pv[4] = {0.f, 0.f, 0.f, 0.f};
    if (wr) { pv[0] = prow[0]; pv[1] = prow[U_]; pv[2] = prow[2 * U_]; pv[3] = prow[3 * U_]; }
    __syncthreads();

    const int ksoff = ks * 72;

    for (int t = 0; t < T_; t++) {
        float pn[4] = {0.f, 0.f, 0.f, 0.f};
        if (wr) {
            int tn = (t < T_ - 1) ? t + 1 : t;
            const float* pp = prow + (size_t)tn * B_ * U_;
            pn[0] = pp[0]; pn[1] = pp[U_]; pn[2] = pp[2 * U_]; pn[3] = pp[3 * U_];
        }

        const float* hb = hs[t & 1];
        float*       hn = hs[(t + 1) & 1];

        ull acc[4] = {0ULL, 0ULL, 0ULL, 0ULL};
#pragma unroll
        for (int r = 0; r < 4; r++) {
            const char* base = (const char*)(hb + r * RSTR + ksoff);
#pragma unroll
            for (int half = 0; half < 2; half++) {
#pragma unroll
                for (int i = 0; i < 8; i++) {
                    ulonglong2 hv = *(const ulonglong2*)(base + half * 144 + i * 16);
                    fma2(acc[r], hv.x, wp[half * 16 + 2 * i]);
                    fma2(acc[r], hv.y, wp[half * 16 + 2 * i + 1]);
                }
            }
        }

        float s[4];
#pragma unroll
        for (int r = 0; r < 4; r++) {
            uint lo = (uint)acc[r], hi = (uint)(acc[r] >> 32);
            uint plo = __shfl_xor_sync(0xffffffffu, lo, 1);
            uint phi = __shfl_xor_sync(0xffffffffu, hi, 1);
            float flo = __uint_as_float(lo) + __uint_as_float(plo);
            float fhi = __uint_as_float(hi) + __uint_as_float(phi);
            s[r] = fmaxf(flo + fhi + pv[r], 0.f);
        }

        if (wr) {
#pragma unroll
            for (int r = 0; r < 4; r++) {
                hn[r * RSTR + uph] = s[r];
                if (STOREH)
                    hall[((size_t)t * B_ + r0 + r) * U_ + u] = s[r];
                pv[r] = pn[r];
            }
        }
        __syncthreads();
    }

    if (FINAL) {
        if (wr) {
            float wd = Wd[u];
            const float* hf = hs[0];
            part_s[u] = make_float4(hf[0 * RSTR + uph] * wd, hf[1 * RSTR + uph] * wd,
                                    hf[2 * RSTR + uph] * wd, hf[3 * RSTR + uph] * wd);
        }
        __syncthreads();
        if (tid < 4) {
            float ssum = 0.f;
            for (int i = 0; i < U_; i++) ssum += ((const float*)(part_s + i))[tid];
            dout[r0 + tid] = ssum + bd[0];
        }
    }
}

// ============================================================================
// Fused B+C: h1 recurrence + p2 = h1 @ Wx2 + b2, computed from the SAME
// broadcast LDS of h (zero extra wavefronts, +128 FFMA2/thread -> fills the
// measured ~500-cyc fma slack under the 1024-wf/step crossbar budget).
// At iter t we read hb = h_{t-1}: accumulate BOTH the Wh1 mma (-> h_t) and the
// Wx2 mma (-> p2 row t-1, lagged off the critical chain). Loop runs t=0..T
// inclusive: t=T does only the p2 tail for h_{T-1}; t=0 skips the p2 store.
// ============================================================================
__global__ __launch_bounds__(256, 1)
void recurBC(const float* __restrict__ p, const float* __restrict__ Wh,
             const float* __restrict__ Wx2c, const float* __restrict__ b2,
             float* __restrict__ p2out)
{
    __shared__ __align__(16) float hs[2][4 * RSTR];

    const int tid = threadIdx.x;
    const int u   = tid >> 1;
    const int ks  = tid & 1;
    const int r0  = blockIdx.x * 4;
    const bool wr = (ks == 0);

    ull wp[32], wq[32];
#pragma unroll
    for (int i = 0; i < 32; i++) {
        int k = ks * 64 + 2 * i;
        wp[i] = pack2(Wh[(size_t)k * U_ + u],   Wh[(size_t)(k + 1) * U_ + u]);
        wq[i] = pack2(Wx2c[(size_t)k * U_ + u], Wx2c[(size_t)(k + 1) * U_ + u]);
    }
    const float b2v = b2[u];

    for (int i = tid; i < 4 * RSTR; i += 256) hs[0][i] = 0.f;

    const int uph = u + 4 * (u >> 5);

    const float* prow = p + (size_t)r0 * U_ + u;
    float pv[4] = {0.f, 0.f, 0.f, 0.f};
    if (wr) { pv[0] = prow[0]; pv[1] = prow[U_]; pv[2] = prow[2 * U_]; pv[3] = prow[3 * U_]; }
    __syncthreads();

    const int ksoff = ks * 72;

    for (int t = 0; t <= T_; t++) {
        float pn[4] = {0.f, 0.f, 0.f, 0.f};
        if (wr) {
            int tn = (t < T_ - 1) ? t + 1 : T_ - 1;
            const float* pp = prow + (size_t)tn * B_ * U_;
            pn[0] = pp[0]; pn[1] = pp[U_]; pn[2] = pp[2 * U_]; pn[3] = pp[3 * U_];
        }

        const float* hb = hs[t & 1];
        float*       hn = hs[(t + 1) & 1];

        ull acc[4]  = {0ULL, 0ULL, 0ULL, 0ULL};   // Wh1 mma  -> h_t
        ull bacc[4] = {0ULL, 0ULL, 0ULL, 0ULL};   // Wx2 mma  -> p2[t-1]
#pragma unroll
        for (int r = 0; r < 4; r++) {
            const char* base = (const char*)(hb + r * RSTR + ksoff);
#pragma unroll
            for (int half = 0; half < 2; half++) {
#pragma unroll
                for (int i = 0; i < 8; i++) {
                    ulonglong2 hv = *(const ulonglong2*)(base + half * 144 + i * 16);
                    ull wA = wp[half * 16 + 2 * i], wB = wp[half * 16 + 2 * i + 1];
                    ull qA = wq[half * 16 + 2 * i], qB = wq[half * 16 + 2 * i + 1];
                    fma2(acc[r],  hv.x, wA);
                    fma2(acc[r],  hv.y, wB);
                    fma2(bacc[r], hv.x, qA);
                    fma2(bacc[r], hv.y, qB);
                }
            }
        }

        // cross-slice reduction (lane ^ 1) for both accumulator sets
        float s[4], q[4];
#pragma unroll
        for (int r = 0; r < 4; r++) {
            uint lo = (uint)acc[r], hi = (uint)(acc[r] >> 32);
            uint plo = __shfl_xor_sync(0xffffffffu, lo, 1);
            uint phi = __shfl_xor_sync(0xffffffffu, hi, 1);
            s[r] = __uint_as_float(lo) + __uint_as_float(plo)
                 + __uint_as_float(hi) + __uint_as_float(phi);

            uint blo = (uint)bacc[r], bhi = (uint)(bacc[r] >> 32);
            uint pblo = __shfl_xor_sync(0xffffffffu, blo, 1);
            uint pbhi = __shfl_xor_sync(0xffffffffu, bhi, 1);
            q[r] = __uint_as_float(blo) + __uint_as_float(pblo)
                 + __uint_as_float(bhi) + __uint_as_float(pbhi) + b2v;
        }

        if (wr) {
            if (t > 0) {
                float* po = p2out + ((size_t)(t - 1) * B_ + r0) * U_ + u;
                po[0] = q[0]; po[U_] = q[1]; po[2 * U_] = q[2]; po[3 * U_] = q[3];
            }
            if (t < T_) {
#pragma unroll
                for (int r = 0; r < 4; r++) {
                    float hv = fmaxf(s[r] + pv[r], 0.f);
                    hn[r * RSTR + uph] = hv;
                    pv[r] = pn[r];
                }
            }
        }
        __syncthreads();
    }
}

// ============================================================================
extern "C" void kernel_launch(void* const* d_in, const int* in_sizes, int n_in,
                              void* d_out, int out_size)
{
    (void)in_sizes; (void)n_in; (void)out_size;
    const float* x   = (const float*)d_in[0];
    const float* Wx1 = (const float*)d_in[1];
    const float* Wh1 = (const float*)d_in[2];
    const float* b1  = (const float*)d_in[3];
    const float* Wx2 = (const float*)d_in[4];
    const float* Wh2 = (const float*)d_in[5];
    const float* b2  = (const float*)d_in[6];
    const float* Wd  = (const float*)d_in[7];
    const float* bd  = (const float*)d_in[8];
    float* out = (float*)d_out;

    float *pbuf, *p2buf;
    cudaGetSymbolAddress((void**)&pbuf, g_pbuf);
    cudaGetSymbolAddress((void**)&p2buf, g_p2);

    const int ngrid = (T_ * B_) / 64;                        // 8192 tiles
    const int smemA = (64 * U_ + 64 * 68) * sizeof(float);   // 50176 B
    cudaFuncSetAttribute(gemm_bias<64, true>,
                         cudaFuncAttributeMaxDynamicSharedMemorySize, smemA);

    // Phase A: px1 = x @ Wx1 + b1           (layout [t][b][u])
    gemm_bias<64, true><<<ngrid, 256, smemA>>>(x, Wx1, b1, pbuf);
    // Phase B+C fused: h1 recurrence + p2 = h1 @ Wx2 + b2 (GEMM C eliminated)
    recurBC<<<B_ / 4, 256>>>(pbuf, Wh1, Wx2, b2, p2buf);
    // Phase D: h2 recurrence + final projection
    recur2<false, true><<<B_ / 4, 256>>>(p2buf, Wh2, nullptr, Wd, bd, out);
}